// round 4
// baseline (speedup 1.0000x reference)
#include <cuda_runtime.h>
#include <cstdint>

// HaarWaveletTopK on GB300 (sm_103a) — float4 streaming pass1 + warp-parallel pass2.
// x: (B=8, T=8192, F=512) fp32.  out = [main | detail], each (B,T,F).

#define DIM_B 8
#define DIM_T 8192
#define DIM_T2 4096
#define DIM_F 512
#define DIM_F4 (DIM_F / 4)            // 128 float4 per row

#define TOPK 8
#define NCHUNK 32                      // t-chunks per column
#define T_PER_CHUNK (DIM_T2 / NCHUNK)  // 128
#define WARPS 4                        // warps per block (t-split inside chunk)
#define NTHREADS (32 * WARPS)          // 128
#define T_PER_THREAD (T_PER_CHUNK / WARPS)  // 32
#define NCAND (NCHUNK * TOPK)          // 256 candidates per column

typedef unsigned long long u64;
typedef unsigned int u32;

// Packed candidates: [col][q], col = b*512+f, q = chunk*8+j.  8 MB.
__device__ u64 g_cand[DIM_B * DIM_F * NCAND];

__device__ __forceinline__ u64 pack_cand(float a, int p)
{
    return ((u64)__float_as_uint(a) << 32) | (u32)p;
}

// Sorted-descending insert into an 8-entry packed list (caller pre-checks > list[7]).
__device__ __forceinline__ void ins8(u64 (&L)[TOPK], u64 v)
{
    L[7] = v;
#pragma unroll
    for (int j = 7; j > 0; --j) {
        if (L[j] > L[j - 1]) { u64 t = L[j]; L[j] = L[j - 1]; L[j - 1] = t; }
    }
}

// ---------------------------------------------------------------------------
// Pass 1: Haar transform (dense main + zero detail) and per-chunk top-8.
// Thread owns 4 adjacent f-columns (one float4 lane). 128-bit loads/stores.
// ---------------------------------------------------------------------------
__global__ __launch_bounds__(NTHREADS)
void haar_pass1(const float4* __restrict__ x4,
                float4* __restrict__ m4,
                float4* __restrict__ d4)
{
    // [sub][j][ts][lane] — lane contiguous for conflict-free STS/LDS. 32 KB.
    __shared__ u64 s_cand[4][TOPK][WARPS][32];

    const int lane = threadIdx.x & 31;
    const int ts   = threadIdx.x >> 5;            // warp id = t-segment
    const int g    = blockIdx.x * 32 + lane;       // float4 group index (0..127)
    const int b    = blockIdx.y;
    const int c    = blockIdx.z;                   // chunk 0..31

    const float4* __restrict__ xb = x4 + (size_t)b * DIM_T * DIM_F4;
    float4* __restrict__ mb       = m4 + (size_t)b * DIM_T * DIM_F4;
    float4* __restrict__ db       = d4 + (size_t)b * DIM_T * DIM_F4;

    u64 best[4][TOPK];
#pragma unroll
    for (int s = 0; s < 4; ++s)
#pragma unroll
        for (int j = 0; j < TOPK; ++j) best[s][j] = 0;

    const int t0 = c * T_PER_CHUNK + ts * T_PER_THREAD;
    const float4 z4 = make_float4(0.f, 0.f, 0.f, 0.f);

#pragma unroll 2
    for (int i = 0; i < T_PER_THREAD; ++i) {
        const int t = t0 + i;
        const size_t re = (size_t)(2 * t) * DIM_F4 + g;    // even row, float4 units
        const float4 e = xb[re];
        const float4 o = xb[re + DIM_F4];

        float4 low;
        low.x = (e.x + o.x) * 0.5f;
        low.y = (e.y + o.y) * 0.5f;
        low.z = (e.z + o.z) * 0.5f;
        low.w = (e.w + o.w) * 0.5f;

        mb[re]          = low;
        mb[re + DIM_F4] = low;
        db[re]          = z4;
        db[re + DIM_F4] = z4;

        const float hx = e.x - o.x;
        const float hy = e.y - o.y;
        const float hz = e.z - o.z;
        const float hw = e.w - o.w;

        const u64 pkx = pack_cand(fabsf(hx), (t << 1) | (hx < 0.f ? 1 : 0));
        const u64 pky = pack_cand(fabsf(hy), (t << 1) | (hy < 0.f ? 1 : 0));
        const u64 pkz = pack_cand(fabsf(hz), (t << 1) | (hz < 0.f ? 1 : 0));
        const u64 pkw = pack_cand(fabsf(hw), (t << 1) | (hw < 0.f ? 1 : 0));

        if (pkx > best[0][7]) ins8(best[0], pkx);
        if (pky > best[1][7]) ins8(best[1], pky);
        if (pkz > best[2][7]) ins8(best[2], pkz);
        if (pkw > best[3][7]) ins8(best[3], pkw);
    }

    // Publish per-thread lists
#pragma unroll
    for (int s = 0; s < 4; ++s)
#pragma unroll
        for (int j = 0; j < TOPK; ++j)
            s_cand[s][j][ts][lane] = best[s][j];
    __syncthreads();

    // Warp 0: merge the 4 t-segments per column, spill per-chunk top-8.
    if (ts == 0) {
#pragma unroll
        for (int s = 0; s < 4; ++s) {
            u64 mrg[TOPK];
#pragma unroll
            for (int j = 0; j < TOPK; ++j) mrg[j] = 0;

#pragma unroll
            for (int t2 = 0; t2 < WARPS; ++t2)
#pragma unroll
                for (int j = 0; j < TOPK; ++j) {
                    const u64 v = s_cand[s][j][t2][lane];
                    if (v > mrg[7]) ins8(mrg, v);
                }

            const int col = 4 * g + s;                       // 0..511
            const size_t base = ((size_t)(b * DIM_F + col)) * NCAND + (size_t)c * TOPK;
#pragma unroll
            for (int j = 0; j < TOPK; ++j)
                g_cand[base + j] = mrg[j];                   // 64B run per (col,chunk)
        }
    }
}

// ---------------------------------------------------------------------------
// Pass 2: one warp per (b,f) column — merge 256 candidates, scatter 16 values.
// ---------------------------------------------------------------------------
__global__ __launch_bounds__(256)
void haar_pass2(float* __restrict__ out_det)
{
    const int wid_in_blk = threadIdx.x >> 5;
    const int lane       = threadIdx.x & 31;
    const int col        = blockIdx.x * 8 + wid_in_blk;   // 0..4095
    const int b          = col >> 9;
    const int f          = col & (DIM_F - 1);

    const size_t base = (size_t)col * NCAND;

    // Each lane: 8 coalesced candidate loads
    u64 v[8];
#pragma unroll
    for (int r = 0; r < 8; ++r)
        v[r] = g_cand[base + lane + 32 * r];

    // Per-lane sort-8 descending (insertion sort, fully unrolled)
#pragma unroll
    for (int i = 1; i < 8; ++i)
#pragma unroll
        for (int j = i; j > 0; --j)
            if (v[j] > v[j - 1]) { u64 t = v[j]; v[j] = v[j - 1]; v[j - 1] = t; }

    u64 res = 0;   // lane r holds round-r winner
#pragma unroll
    for (int r = 0; r < TOPK; ++r) {
        u64 head = v[0];
#pragma unroll
        for (int off = 16; off > 0; off >>= 1) {
            const u64 other = __shfl_xor_sync(0xFFFFFFFFu, head, off);
            if (other > head) head = other;
        }
        const bool mine = (v[0] == head) && (head != 0);
        const unsigned m = __ballot_sync(0xFFFFFFFFu, mine);
        const int winner = __ffs(m) - 1;
        if (lane == winner) {
#pragma unroll
            for (int j = 0; j < 7; ++j) v[j] = v[j + 1];
            v[7] = 0;
        }
        if (lane == r) res = head;
    }

    // Lanes 0..7 scatter the sparse detail values
    if (lane < TOPK) {
        const u32 payv = (u32)res;
        const float k  = __uint_as_float((u32)(res >> 32));
        float val      = k * 0.5f;                 // |e-o|*0.5 = |high_half|
        if (payv & 1) val = -val;
        const int tt   = payv >> 1;
        float* __restrict__ db = out_det + (size_t)b * DIM_T * DIM_F;
        const size_t r0 = (size_t)(2 * tt) * DIM_F + f;
        db[r0]         = val;
        db[r0 + DIM_F] = -val;
    }
}

extern "C" void kernel_launch(void* const* d_in, const int* in_sizes, int n_in,
                              void* d_out, int out_size)
{
    const float* x = (const float*)d_in[0];
    float* out = (float*)d_out;
    const size_t N = (size_t)out_size / 2;   // elements in `main`

    dim3 grid1(DIM_F4 / 32, DIM_B, NCHUNK);   // 4 x 8 x 32 = 1024 blocks
    haar_pass1<<<grid1, NTHREADS>>>((const float4*)x,
                                    (float4*)out,
                                    (float4*)(out + N));

    haar_pass2<<<DIM_B * DIM_F / 8, 256>>>(out + N);   // 512 blocks
}

// round 5
// speedup vs baseline: 1.2825x; 1.2825x over previous
#include <cuda_runtime.h>
#include <cstdint>

// HaarWaveletTopK on GB300 (sm_103a)
// Pass1: R2's proven scalar streaming loop (1 f-column per thread).
// Pass2: warp-per-column candidate merge + sparse scatter.
// x: (B=8, T=8192, F=512) fp32.  out = [main | detail], each (B,T,F).

#define DIM_B 8
#define DIM_T 8192
#define DIM_T2 4096
#define DIM_F 512

#define TOPK 8
#define NC 16                          // t-chunks per column
#define T_PER_CHUNK (DIM_T2 / NC)      // 256
#define FT 32                          // f-columns per block (warp width)
#define TSEG 8                         // warps per block (t-split inside chunk)
#define NTHREADS (FT * TSEG)           // 256
#define T_PER_THREAD (T_PER_CHUNK / TSEG)  // 32
#define NCAND (NC * TOPK)              // 128 candidates per column

typedef unsigned long long u64;
typedef unsigned int u32;

// Packed candidates: [col][q], col = b*512+f, q = chunk*8+j.  4 MB.
__device__ u64 g_cand[DIM_B * DIM_F * NCAND];

__device__ __forceinline__ u64 pack_cand(float k, int p)
{
    return ((u64)__float_as_uint(k) << 32) | (u32)p;   // k >= 0 -> monotone
}

// ---------------------------------------------------------------------------
// Pass 1: Haar transform, dense outputs, per-chunk top-8 partials.
// (Hot loop identical to the R2 kernel that measured ~89 us.)
// ---------------------------------------------------------------------------
__global__ __launch_bounds__(NTHREADS)
void haar_pass1(const float* __restrict__ x,
                float* __restrict__ out_main,
                float* __restrict__ out_det)
{
    __shared__ float s_key[FT][TSEG * TOPK + 1];
    __shared__ int   s_pay[FT][TSEG * TOPK + 1];

    const int lane_f = threadIdx.x & (FT - 1);     // consecutive f within warp
    const int ts     = threadIdx.x >> 5;           // warp id = t-segment, 0..7
    const int f      = blockIdx.x * FT + lane_f;
    const int b      = blockIdx.y;
    const int c      = blockIdx.z;                 // chunk id, 0..NC-1

    const float* __restrict__ xb = x        + (size_t)b * DIM_T * DIM_F;
    float* __restrict__ mb       = out_main + (size_t)b * DIM_T * DIM_F;
    float* __restrict__ db       = out_det  + (size_t)b * DIM_T * DIM_F;

    float key[TOPK];
    int   pay[TOPK];
#pragma unroll
    for (int j = 0; j < TOPK; ++j) { key[j] = 0.0f; pay[j] = 0; }

    const int t0 = c * T_PER_CHUNK + ts * T_PER_THREAD;

#pragma unroll 4
    for (int i = 0; i < T_PER_THREAD; ++i) {
        const int t = t0 + i;
        const size_t re = (size_t)(2 * t) * DIM_F + f;   // even row
        const float e = xb[re];
        const float o = xb[re + DIM_F];

        const float low = (e + o) * 0.5f;
        const float h   = e - o;                          // ∝ x_high

        mb[re]          = low;
        mb[re + DIM_F]  = low;
        db[re]          = 0.0f;
        db[re + DIM_F]  = 0.0f;

        const float a = fabsf(h);
        if (a > key[TOPK - 1]) {
            key[TOPK - 1] = a;
            pay[TOPK - 1] = (t << 1) | (h < 0.0f ? 1 : 0);
#pragma unroll
            for (int j = TOPK - 1; j > 0; --j) {
                if (key[j] > key[j - 1]) {
                    float tk = key[j]; key[j] = key[j - 1]; key[j - 1] = tk;
                    int   tp = pay[j]; pay[j] = pay[j - 1]; pay[j - 1] = tp;
                }
            }
        }
    }

    // Publish per-thread candidates
#pragma unroll
    for (int j = 0; j < TOPK; ++j) {
        s_key[lane_f][ts * TOPK + j] = key[j];
        s_pay[lane_f][ts * TOPK + j] = pay[j];
    }
    __syncthreads();

    // Warp 0: one thread per column merges 64 candidates, spills packed top-8.
    if (ts == 0) {
        float bk[TOPK];
        int   bp[TOPK];
#pragma unroll
        for (int j = 0; j < TOPK; ++j) { bk[j] = 0.0f; bp[j] = 0; }

#pragma unroll 4
        for (int q = 0; q < TSEG * TOPK; ++q) {
            const float a = s_key[lane_f][q];
            if (a > bk[TOPK - 1]) {
                bk[TOPK - 1] = a;
                bp[TOPK - 1] = s_pay[lane_f][q];
#pragma unroll
                for (int j = TOPK - 1; j > 0; --j) {
                    if (bk[j] > bk[j - 1]) {
                        float tk = bk[j]; bk[j] = bk[j - 1]; bk[j - 1] = tk;
                        int   tp = bp[j]; bp[j] = bp[j - 1]; bp[j - 1] = tp;
                    }
                }
            }
        }

        // Column-major scratch so pass2 reads are coalesced.
        const size_t base = ((size_t)(b * DIM_F + f)) * NCAND + (size_t)c * TOPK;
#pragma unroll
        for (int j = 0; j < TOPK; ++j)
            g_cand[base + j] = pack_cand(bk[j], bp[j]);
    }
}

// ---------------------------------------------------------------------------
// Pass 2: one warp per (b,f) column — merge 128 candidates, scatter 16 values.
// ---------------------------------------------------------------------------
__global__ __launch_bounds__(256)
void haar_pass2(float* __restrict__ out_det)
{
    const int wid_in_blk = threadIdx.x >> 5;
    const int lane       = threadIdx.x & 31;
    const int col        = blockIdx.x * 8 + wid_in_blk;   // 0..4095
    const int b          = col >> 9;
    const int f          = col & (DIM_F - 1);

    const size_t base = (size_t)col * NCAND;

    // Each lane: 4 coalesced candidate loads
    u64 v0 = g_cand[base + lane];
    u64 v1 = g_cand[base + lane + 32];
    u64 v2 = g_cand[base + lane + 64];
    u64 v3 = g_cand[base + lane + 96];

    // Sort 4 descending (network)
    u64 t;
    if (v0 < v1) { t = v0; v0 = v1; v1 = t; }
    if (v2 < v3) { t = v2; v2 = v3; v3 = t; }
    if (v0 < v2) { t = v0; v0 = v2; v2 = t; }
    if (v1 < v3) { t = v1; v1 = v3; v3 = t; }
    if (v1 < v2) { t = v1; v1 = v2; v2 = t; }

    u64 res = 0;   // lane r holds round-r winner
#pragma unroll
    for (int r = 0; r < TOPK; ++r) {
        u64 head = v0;
#pragma unroll
        for (int off = 16; off > 0; off >>= 1) {
            const u64 other = __shfl_xor_sync(0xFFFFFFFFu, head, off);
            if (other > head) head = other;
        }
        const bool mine = (v0 == head) && (head != 0);
        const unsigned m = __ballot_sync(0xFFFFFFFFu, mine);
        const int winner = __ffs(m) - 1;
        if (lane == winner) { v0 = v1; v1 = v2; v2 = v3; v3 = 0; }
        if (lane == r) res = head;
    }

    // Lanes 0..7 scatter the sparse detail values
    if (lane < TOPK) {
        const u32 payv = (u32)res;
        const float k  = __uint_as_float((u32)(res >> 32));
        float val      = k * 0.5f;                 // |e-o|*0.5 = |high_half|
        if (payv & 1) val = -val;
        const int tt   = payv >> 1;
        float* __restrict__ db = out_det + (size_t)b * DIM_T * DIM_F;
        const size_t r0 = (size_t)(2 * tt) * DIM_F + f;
        db[r0]         = val;
        db[r0 + DIM_F] = -val;
    }
}

extern "C" void kernel_launch(void* const* d_in, const int* in_sizes, int n_in,
                              void* d_out, int out_size)
{
    const float* x = (const float*)d_in[0];
    float* out = (float*)d_out;
    const size_t N = (size_t)out_size / 2;   // elements in `main`

    dim3 grid1(DIM_F / FT, DIM_B, NC);       // 16 x 8 x 16 = 2048 blocks
    haar_pass1<<<grid1, NTHREADS>>>(x, out, out + N);

    haar_pass2<<<DIM_B * DIM_F / 8, 256>>>(out + N);   // 512 blocks
}